// round 1
// baseline (speedup 1.0000x reference)
#include <cuda_runtime.h>
#include <math.h>

// Shapelet_66932770341112
// B=16, C=8, T=512, L=24, STRIDE=2, N=64, M=245, EPS=1
// out[0 : B*N*C]         = max_p(b,n,c) = exp(-min_m d^2)
// out[B*N*C : 2*B*N*C]   = d_min(b,n,c) = min_m d
// where d(b,m,n,c) = (1/L) * sum_l |x[b,c,2m+l] - w[n,c,l]| * pcm[c,m]

#define BB 16
#define CC 8
#define TT 512
#define LL 24
#define NN 64
#define MM 245

__global__ __launch_bounds__(256, 8)
void shapelet_kernel(const float* __restrict__ x,
                     const float* __restrict__ w,
                     const float* __restrict__ pcm,
                     float* __restrict__ out)
{
    // Even/odd split of the x row: x[2*t] -> xe[t], x[2*t+1] -> xo[t].
    // Then x[2m+l] = (l even) ? xe[m + l/2] : xo[m + l/2]  -> conflict-free LDS
    // (consecutive lanes have consecutive m).
    __shared__ float xe[256];
    __shared__ float xo[256];
    __shared__ float pen[256];

    const int bc   = blockIdx.x;          // b*C + c
    const int b    = bc >> 3;             // / CC
    const int c    = bc & 7;              // % CC
    const int tid  = threadIdx.x;
    const int lane = tid & 31;
    const int warp = tid >> 5;

    const float* xrow = x + bc * TT;
    xe[tid] = xrow[2 * tid];
    xo[tid] = xrow[2 * tid + 1];
    pen[tid] = (tid < MM) ? pcm[c * MM + tid] : 0.0f;
    __syncthreads();

    const int n = blockIdx.y * 8 + warp;  // one warp per shapelet n
    const float* wr = w + (n * CC + c) * LL;
    float wreg[LL];
#pragma unroll
    for (int l = 0; l < LL; ++l) wreg[l] = __ldg(wr + l);

    float dmin  = INFINITY;   // min over m of d (signed; penalty could be anything)
    float d2min = INFINITY;   // min over m of d^2  ->  max_p = exp(-d2min)

#pragma unroll
    for (int mi = 0; mi < 8; ++mi) {
        const int m = lane + mi * 32;
        if (m < MM) {
            float s = 0.0f;
#pragma unroll
            for (int l = 0; l < LL; l += 2) {
                s += fabsf(xe[m + (l >> 1)] - wreg[l]);
                s += fabsf(xo[m + (l >> 1)] - wreg[l + 1]);
            }
            const float d = s * (1.0f / (float)LL) * pen[m];
            dmin  = fminf(dmin, d);
            d2min = fminf(d2min, d * d);
        }
    }

    // warp reduction over the 32 lanes (covering all M positions)
#pragma unroll
    for (int off = 16; off; off >>= 1) {
        dmin  = fminf(dmin,  __shfl_xor_sync(0xffffffffu, dmin,  off));
        d2min = fminf(d2min, __shfl_xor_sync(0xffffffffu, d2min, off));
    }

    if (lane == 0) {
        const int o = (b * NN + n) * CC + c;
        out[o] = expf(-d2min);
        out[BB * NN * CC + o] = dmin;
    }
}

extern "C" void kernel_launch(void* const* d_in, const int* in_sizes, int n_in,
                              void* d_out, int out_size)
{
    const float* x   = (const float*)d_in[0];   // (B, C, T)
    const float* w   = (const float*)d_in[1];   // (N, C, L)
    const float* pcm = (const float*)d_in[2];   // (C, M)
    float* out = (float*)d_out;                  // 2 * B*N*C floats

    dim3 grid(BB * CC, NN / 8);
    shapelet_kernel<<<grid, 256>>>(x, w, pcm, out);
}

// round 2
// speedup vs baseline: 1.1805x; 1.1805x over previous
#include <cuda_runtime.h>
#include <math.h>

// Shapelet_66932770341112 on sm_103a
// B=16, C=8, T=512, L=24, STRIDE=2, N=64, M=245, EPS=1
// d(b,m,n,c) = (1/L) * sum_l |x[b,c,2m+l] - w[n,c,l]| * pcm[c,m]
// out[0 : B*N*C]       = exp(-min_m d^2)
// out[B*N*C : 2*B*N*C] = min_m d

#define BB 16
#define CC 8
#define TT 512
#define LL 24
#define NN 64
#define MM 245
#define NG 8              // shapelets per block
#define LP (LL/2)         // 12 float2 pairs

__device__ __forceinline__ unsigned long long add_f32x2(unsigned long long a,
                                                        unsigned long long b) {
    unsigned long long r;
    asm("add.rn.f32x2 %0, %1, %2;" : "=l"(r) : "l"(a), "l"(b));
    return r;
}

__global__ __launch_bounds__(256, 4)
void shapelet_kernel(const float* __restrict__ x,
                     const float* __restrict__ w,
                     const float* __restrict__ pcm,
                     float* __restrict__ out)
{
    // x row as float2 pairs: xsm[t] = (x[2t], x[2t+1]); padded so the window
    // read for m up to 255 stays in bounds.
    __shared__ unsigned long long xsm[256 + LP];       // 268 float2
    __shared__ unsigned long long wneg[NG][LP];        // negated weight pairs
    __shared__ float dsm[NG][256];                     // staged d(m, n_local)

    const int bc   = blockIdx.x;      // b*C + c
    const int b    = bc >> 3;
    const int c    = bc & 7;
    const int n0   = blockIdx.y * NG; // first shapelet of this block
    const int tid  = threadIdx.x;
    const int lane = tid & 31;
    const int warp = tid >> 5;

    // ---- load x row (512 floats = 256 float2), pad tail with zeros ----
    const float2* xrow = (const float2*)(x + bc * TT);
    ((float2*)xsm)[tid] = xrow[tid];
    if (tid < LP) ((float2*)xsm)[256 + tid] = make_float2(0.f, 0.f);

    // ---- load 8 shapelets' weights for channel c, negated ----
    if (tid < NG * LL) {
        const int j = tid / LL;
        const int l = tid % LL;
        ((float*)wneg)[j * LL + l] = -w[((n0 + j) * CC + c) * LL + l];
    }
    __syncthreads();

    // ---- per-thread x window in registers (24 regs) ----
    unsigned long long xw[LP];
#pragma unroll
    for (int k = 0; k < LP; ++k) xw[k] = xsm[tid + k];

    // penalty * (1/L), premultiplied; 0 for padding threads (d forced to INF below)
    const float pen = (tid < MM) ? pcm[c * MM + tid] * (1.0f / (float)LL) : 0.0f;
    const float INF = __int_as_float(0x7f800000);

    const unsigned long long ABS2 = 0x7fffffff7fffffffULL;

    // ---- main loop: 8 shapelets, packed abs-diff accumulation ----
#pragma unroll
    for (int j = 0; j < NG; ++j) {
        unsigned long long acc0 = 0ULL, acc1 = 0ULL;
#pragma unroll
        for (int k = 0; k < LP; k += 2) {
            unsigned long long t0 = add_f32x2(xw[k],     wneg[j][k])     & ABS2;
            unsigned long long t1 = add_f32x2(xw[k + 1], wneg[j][k + 1]) & ABS2;
            acc0 = add_f32x2(acc0, t0);
            acc1 = add_f32x2(acc1, t1);
        }
        acc0 = add_f32x2(acc0, acc1);
        const float s = __int_as_float((unsigned)(acc0 & 0xffffffffULL)) +
                        __int_as_float((unsigned)(acc0 >> 32));
        const float d = s * pen;
        dsm[j][tid] = (tid < MM) ? d : INF;
    }
    __syncthreads();

    // ---- reduction: warp j reduces n_local = j over all 256 staged values ----
    float dmin = INF, d2min = INF;
    const float* row = dsm[warp];
#pragma unroll
    for (int i = 0; i < 8; ++i) {
        const float v = row[lane + i * 32];
        dmin  = fminf(dmin, v);
        d2min = fminf(d2min, v * v);
    }
#pragma unroll
    for (int off = 16; off; off >>= 1) {
        dmin  = fminf(dmin,  __shfl_xor_sync(0xffffffffu, dmin,  off));
        d2min = fminf(d2min, __shfl_xor_sync(0xffffffffu, d2min, off));
    }
    if (lane == 0) {
        const int n = n0 + warp;
        const int o = (b * NN + n) * CC + c;
        out[o] = expf(-d2min);
        out[BB * NN * CC + o] = dmin;
    }
}

extern "C" void kernel_launch(void* const* d_in, const int* in_sizes, int n_in,
                              void* d_out, int out_size)
{
    const float* x   = (const float*)d_in[0];   // (B, C, T)
    const float* w   = (const float*)d_in[1];   // (N, C, L)
    const float* pcm = (const float*)d_in[2];   // (C, M)
    float* out = (float*)d_out;

    dim3 grid(BB * CC, NN / NG);                // 128 x 8 = 1024 blocks
    shapelet_kernel<<<grid, 256>>>(x, w, pcm, out);
}